// round 1
// baseline (speedup 1.0000x reference)
#include <cuda_runtime.h>

#define B_  2
#define S_  2048
#define D_  1024
#define H_  16
#define DK_ 64
#define BS_ (B_*S_)    // 4096
#define HD_ (H_*DK_)   // 1024

// Scratch (allocation-free rule: __device__ globals). 4 x 16MB = 64MB.
__device__ float g_q[B_*H_*S_*DK_];
__device__ float g_k[B_*H_*S_*DK_];
__device__ float g_v[B_*H_*S_*DK_];
__device__ float g_att[B_*H_*S_*DK_];

// ---------------------------------------------------------------------------
// Kernel 1: QKV projections.
//   q[b,h,s,k] = sum_d X[b,s,d] * W[h,d,k]
// As a GEMM: M=BS=4096, N=H*DK=1024, K=D=1024 with head-reindexed B/C.
// 128x128x8 tile, 256 threads, 8x8 micro-tile. grid.z picks (X,W,Out).
// ---------------------------------------------------------------------------
__global__ void __launch_bounds__(256) proj_kernel(
    const float* __restrict__ Xq, const float* __restrict__ Xk, const float* __restrict__ Xv,
    const float* __restrict__ Wq, const float* __restrict__ Wk, const float* __restrict__ Wv)
{
    __shared__ __align__(16) float As[8][128];
    __shared__ __align__(16) float Bs[8][128];

    const float* X; const float* W; float* O;
    if (blockIdx.z == 0)      { X = Xq; W = Wq; O = g_q; }
    else if (blockIdx.z == 1) { X = Xk; W = Wk; O = g_k; }
    else                      { X = Xv; W = Wv; O = g_v; }

    const int n0 = blockIdx.x * 128;
    const int m0 = blockIdx.y * 128;
    const int t  = threadIdx.x;
    const int tx = t & 15, ty = t >> 4;

    float acc[8][8];
    #pragma unroll
    for (int i = 0; i < 8; i++)
        #pragma unroll
        for (int j = 0; j < 8; j++) acc[i][j] = 0.f;

    for (int k0 = 0; k0 < D_; k0 += 8) {
        // A tile: As[kk][m] (transposed store)
        {
            const int mloc = t >> 1;
            const int kc   = (t & 1) * 4;
            float4 v = *reinterpret_cast<const float4*>(&X[(m0 + mloc) * D_ + k0 + kc]);
            As[kc + 0][mloc] = v.x; As[kc + 1][mloc] = v.y;
            As[kc + 2][mloc] = v.z; As[kc + 3][mloc] = v.w;
        }
        // B tile: Bs[kk][n], W layout [H][D][DK], n = h*64 + kc
        {
            const int nloc = (t & 31) * 4;
            const int kk   = t >> 5;
            const int n    = n0 + nloc;
            float4 v = *reinterpret_cast<const float4*>(
                &W[(n >> 6) * (D_ * DK_) + (k0 + kk) * DK_ + (n & 63)]);
            *reinterpret_cast<float4*>(&Bs[kk][nloc]) = v;
        }
        __syncthreads();

        #pragma unroll
        for (int kk = 0; kk < 8; kk++) {
            float a[8], b[8];
            #pragma unroll
            for (int i = 0; i < 8; i++) a[i] = As[kk][ty * 8 + i];
            #pragma unroll
            for (int j = 0; j < 8; j++) b[j] = Bs[kk][tx * 8 + j];
            #pragma unroll
            for (int i = 0; i < 8; i++)
                #pragma unroll
                for (int j = 0; j < 8; j++)
                    acc[i][j] += a[i] * b[j];
        }
        __syncthreads();
    }

    // Store to [B,H,S,DK]
    #pragma unroll
    for (int i = 0; i < 8; i++) {
        const int m_g = m0 + ty * 8 + i;
        const int bb  = m_g >> 11;         // / S_
        const int ss  = m_g & (S_ - 1);
        #pragma unroll
        for (int j = 0; j < 8; j += 4) {
            const int n_g = n0 + tx * 8 + j;
            const int h   = n_g >> 6;
            const int kc  = n_g & 63;
            float4 v = make_float4(acc[i][j], acc[i][j+1], acc[i][j+2], acc[i][j+3]);
            *reinterpret_cast<float4*>(&O[((bb * H_ + h) * S_ + ss) * DK_ + kc]) = v;
        }
    }
}

// ---------------------------------------------------------------------------
// Kernel 2: causal flash attention per (b,h). Block = 64-query tile.
// 256 threads as 16x16, 4x4 micro-tile over [64 rows x 64 cols].
// Qs/Ks stored [d][row] (transposed) for conflict-free LDS; P reuses Ks buf.
// Static smem = 3 * 64*64*4 = 49152 B (exactly the 48KB static limit).
// ---------------------------------------------------------------------------
__global__ void __launch_bounds__(256) attn_kernel()
{
    __shared__ __align__(16) float Qs[64][64];   // [d][row]
    __shared__ __align__(16) float KPs[64][64];  // Ks^T [d][col], then P [row][col]
    __shared__ __align__(16) float Vs[64][64];   // [row][d]

    const int qt = blockIdx.x;          // query tile 0..31
    const int bh = blockIdx.y;          // b*H + h, 0..31
    const int t  = threadIdx.x;
    const int tx = t & 15, ty = t >> 4;

    const float* qbase = g_q + (size_t)bh * S_ * DK_;
    const float* kbase = g_k + (size_t)bh * S_ * DK_;
    const float* vbase = g_v + (size_t)bh * S_ * DK_;

    const int q0 = qt * 64;

    // Load Q tile transposed: Qs[d][row]
    #pragma unroll
    for (int it = 0; it < 4; it++) {
        const int e   = t + it * 256;
        const int row = e >> 4;
        const int dc  = (e & 15) * 4;
        float4 v = *reinterpret_cast<const float4*>(&qbase[(q0 + row) * DK_ + dc]);
        Qs[dc + 0][row] = v.x; Qs[dc + 1][row] = v.y;
        Qs[dc + 2][row] = v.z; Qs[dc + 3][row] = v.w;
    }

    float m_i[4], l_i[4], o[4][4];
    #pragma unroll
    for (int i = 0; i < 4; i++) {
        m_i[i] = -1e30f; l_i[i] = 0.f;
        #pragma unroll
        for (int j = 0; j < 4; j++) o[i][j] = 0.f;
    }

    const float scale = 0.125f;  // 1/sqrt(64)

    for (int kt = 0; kt <= qt; kt++) {
        __syncthreads();   // covers Q load (1st iter) and P/V reads (later iters)
        const int k0 = kt * 64;
        #pragma unroll
        for (int it = 0; it < 4; it++) {
            const int e   = t + it * 256;
            const int row = e >> 4;
            const int dc  = (e & 15) * 4;
            float4 kv = *reinterpret_cast<const float4*>(&kbase[(k0 + row) * DK_ + dc]);
            KPs[dc + 0][row] = kv.x; KPs[dc + 1][row] = kv.y;
            KPs[dc + 2][row] = kv.z; KPs[dc + 3][row] = kv.w;
            float4 vv = *reinterpret_cast<const float4*>(&vbase[(k0 + row) * DK_ + dc]);
            *reinterpret_cast<float4*>(&Vs[row][dc]) = vv;
        }
        __syncthreads();

        // S = Q @ K^T
        float s[4][4];
        #pragma unroll
        for (int i = 0; i < 4; i++)
            #pragma unroll
            for (int j = 0; j < 4; j++) s[i][j] = 0.f;

        #pragma unroll 8
        for (int d = 0; d < 64; d++) {
            float qv[4], kv[4];
            #pragma unroll
            for (int i = 0; i < 4; i++) qv[i] = Qs[d][ty * 4 + i];
            #pragma unroll
            for (int j = 0; j < 4; j++) kv[j] = KPs[d][tx * 4 + j];
            #pragma unroll
            for (int i = 0; i < 4; i++)
                #pragma unroll
                for (int j = 0; j < 4; j++)
                    s[i][j] += qv[i] * kv[j];
        }

        const bool diag = (kt == qt);
        #pragma unroll
        for (int i = 0; i < 4; i++)
            #pragma unroll
            for (int j = 0; j < 4; j++) {
                s[i][j] *= scale;
                if (diag && (tx * 4 + j) > (ty * 4 + i)) s[i][j] = -1e30f;
            }

        // Online softmax (row reductions over the 16 tx-lanes; xor 8/4/2/1
        // stays inside each 16-lane half of the warp).
        #pragma unroll
        for (int i = 0; i < 4; i++) {
            float tm = s[i][0];
            #pragma unroll
            for (int j = 1; j < 4; j++) tm = fmaxf(tm, s[i][j]);
            #pragma unroll
            for (int off = 8; off > 0; off >>= 1)
                tm = fmaxf(tm, __shfl_xor_sync(0xffffffffu, tm, off));

            const float mnew = fmaxf(m_i[i], tm);
            const float corr = __expf(m_i[i] - mnew);
            float rs = 0.f;
            #pragma unroll
            for (int j = 0; j < 4; j++) {
                const float p = __expf(s[i][j] - mnew);
                s[i][j] = p; rs += p;
            }
            #pragma unroll
            for (int off = 8; off > 0; off >>= 1)
                rs += __shfl_xor_sync(0xffffffffu, rs, off);

            l_i[i] = l_i[i] * corr + rs;
            m_i[i] = mnew;
            #pragma unroll
            for (int j = 0; j < 4; j++) o[i][j] *= corr;
        }

        __syncthreads();  // everyone done reading KPs as K^T
        #pragma unroll
        for (int i = 0; i < 4; i++)
            #pragma unroll
            for (int j = 0; j < 4; j++)
                KPs[ty * 4 + i][tx * 4 + j] = s[i][j];
        __syncthreads();

        // O += P @ V
        #pragma unroll 8
        for (int jj = 0; jj < 64; jj++) {
            float pv[4], vv[4];
            #pragma unroll
            for (int i = 0; i < 4; i++) pv[i] = KPs[ty * 4 + i][jj];
            #pragma unroll
            for (int j = 0; j < 4; j++) vv[j] = Vs[jj][tx * 4 + j];
            #pragma unroll
            for (int i = 0; i < 4; i++)
                #pragma unroll
                for (int j = 0; j < 4; j++)
                    o[i][j] += pv[i] * vv[j];
        }
    }

    float* abase = g_att + (size_t)bh * S_ * DK_;
    #pragma unroll
    for (int i = 0; i < 4; i++) {
        const float inv = 1.0f / l_i[i];
        const int row = q0 + ty * 4 + i;
        float4 v = make_float4(o[i][0] * inv, o[i][1] * inv, o[i][2] * inv, o[i][3] * inv);
        *reinterpret_cast<float4*>(&abase[row * DK_ + tx * 4]) = v;
    }
}

// ---------------------------------------------------------------------------
// Kernel 3: output projection.  Out[m,n] = sum_j A[m,j]*Wo[n,j] + bo[n]
// A = g_att with [B,H,S,DK] -> [m, j=h*64+k] reindex. M=4096,N=1024,K=1024.
// ---------------------------------------------------------------------------
__global__ void __launch_bounds__(256) oproj_kernel(
    const float* __restrict__ Wo, const float* __restrict__ bo, float* __restrict__ Out)
{
    __shared__ __align__(16) float As[8][128];
    __shared__ __align__(16) float Bs[8][128];

    const int n0 = blockIdx.x * 128;
    const int m0 = blockIdx.y * 128;
    const int t  = threadIdx.x;
    const int tx = t & 15, ty = t >> 4;

    float acc[8][8];
    #pragma unroll
    for (int i = 0; i < 8; i++)
        #pragma unroll
        for (int j = 0; j < 8; j++) acc[i][j] = 0.f;

    for (int k0 = 0; k0 < HD_; k0 += 8) {
        // A tile: As[kk][m] from g_att
        {
            const int mloc = t >> 1;
            const int kc4  = (t & 1) * 4;
            const int m_g  = m0 + mloc;
            const int bb   = m_g >> 11;
            const int ss   = m_g & (S_ - 1);
            const int j    = k0 + kc4;
            float4 v = *reinterpret_cast<const float4*>(
                &g_att[((bb * H_ + (j >> 6)) * S_ + ss) * DK_ + (j & 63)]);
            As[kc4 + 0][mloc] = v.x; As[kc4 + 1][mloc] = v.y;
            As[kc4 + 2][mloc] = v.z; As[kc4 + 3][mloc] = v.w;
        }
        // B tile: Bs[kk][n] = Wo[n][k] (transpose load along j)
        {
            const int nloc = t >> 1;
            const int kc4  = (t & 1) * 4;
            float4 v = *reinterpret_cast<const float4*>(&Wo[(n0 + nloc) * HD_ + k0 + kc4]);
            Bs[kc4 + 0][nloc] = v.x; Bs[kc4 + 1][nloc] = v.y;
            Bs[kc4 + 2][nloc] = v.z; Bs[kc4 + 3][nloc] = v.w;
        }
        __syncthreads();

        #pragma unroll
        for (int kk = 0; kk < 8; kk++) {
            float a[8], b[8];
            #pragma unroll
            for (int i = 0; i < 8; i++) a[i] = As[kk][ty * 8 + i];
            #pragma unroll
            for (int j = 0; j < 8; j++) b[j] = Bs[kk][tx * 8 + j];
            #pragma unroll
            for (int i = 0; i < 8; i++)
                #pragma unroll
                for (int j = 0; j < 8; j++)
                    acc[i][j] += a[i] * b[j];
        }
        __syncthreads();
    }

    #pragma unroll
    for (int i = 0; i < 8; i++) {
        const int m_g = m0 + ty * 8 + i;
        #pragma unroll
        for (int j = 0; j < 8; j += 4) {
            const int n_g = n0 + tx * 8 + j;
            float4 bv = *reinterpret_cast<const float4*>(&bo[n_g]);
            float4 v = make_float4(acc[i][j] + bv.x, acc[i][j+1] + bv.y,
                                   acc[i][j+2] + bv.z, acc[i][j+3] + bv.w);
            *reinterpret_cast<float4*>(&Out[(size_t)m_g * D_ + n_g]) = v;
        }
    }
}

// ---------------------------------------------------------------------------
// Launch. Inputs (metadata order): query, key, value, Wq, Wk, Wv, Wo, bo.
// ---------------------------------------------------------------------------
extern "C" void kernel_launch(void* const* d_in, const int* in_sizes, int n_in,
                              void* d_out, int out_size)
{
    const float* query = (const float*)d_in[0];
    const float* key   = (const float*)d_in[1];
    const float* value = (const float*)d_in[2];
    const float* Wq    = (const float*)d_in[3];
    const float* Wk    = (const float*)d_in[4];
    const float* Wv    = (const float*)d_in[5];
    const float* Wo    = (const float*)d_in[6];
    const float* bo    = (const float*)d_in[7];
    float* out = (float*)d_out;

    proj_kernel<<<dim3(HD_ / 128, BS_ / 128, 3), 256>>>(query, key, value, Wq, Wk, Wv);
    attn_kernel<<<dim3(S_ / 64, B_ * H_), 256>>>();
    oproj_kernel<<<dim3(D_ / 128, BS_ / 128), 256>>>(Wo, bo, out);
}

// round 3
// speedup vs baseline: 1.5276x; 1.5276x over previous
#include <cuda_runtime.h>
#include <cuda_bf16.h>
#include <cstdint>

#define B_  2
#define S_  2048
#define D_  1024
#define H_  16
#define DK_ 64
#define BS_ (B_*S_)    // 4096
#define HD_ (H_*DK_)   // 1024

// ---------------- scratch (__device__ globals; no allocs allowed) ----------
__device__ float g_q[B_*H_*S_*DK_];
__device__ float g_k[B_*H_*S_*DK_];
__device__ float g_v[B_*H_*S_*DK_];
__device__ float g_att[B_*H_*S_*DK_];

__device__ __nv_bfloat16 g_xh[3*BS_*D_];   // q,k,v inputs, hi
__device__ __nv_bfloat16 g_xl[3*BS_*D_];   // lo
__device__ __nv_bfloat16 g_wh[3*HD_*D_];   // Wq/Wk/Wv transposed to [n][d], hi
__device__ __nv_bfloat16 g_wl[3*HD_*D_];
__device__ __nv_bfloat16 g_ah[BS_*HD_];    // attention output reindexed [m][j]
__device__ __nv_bfloat16 g_al[BS_*HD_];
__device__ __nv_bfloat16 g_woh[D_*HD_];    // Wo [n][j] (already K-major)
__device__ __nv_bfloat16 g_wol[D_*HD_];

// ---------------- helpers ---------------------------------------------------
__device__ __forceinline__ uint32_t smem_u32(const void* p) {
    uint32_t a;
    asm("{ .reg .u64 t; cvta.to.shared.u64 t, %1; cvt.u32.u64 %0, t; }" : "=r"(a) : "l"(p));
    return a;
}
__device__ __forceinline__ void cp16(uint32_t s, const void* g) {
    asm volatile("cp.async.cg.shared.global [%0], [%1], 16;" :: "r"(s), "l"(g) : "memory");
}
__device__ __forceinline__ void ldsm4(uint32_t* r, uint32_t a) {
    asm volatile("ldmatrix.sync.aligned.m8n8.x4.shared.b16 {%0,%1,%2,%3}, [%4];"
                 : "=r"(r[0]), "=r"(r[1]), "=r"(r[2]), "=r"(r[3]) : "r"(a));
}
__device__ __forceinline__ void ldsm2(uint32_t* r, uint32_t a) {
    asm volatile("ldmatrix.sync.aligned.m8n8.x2.shared.b16 {%0,%1}, [%2];"
                 : "=r"(r[0]), "=r"(r[1]) : "r"(a));
}
__device__ __forceinline__ void mma16816(float* d, const uint32_t* a, const uint32_t* b) {
    asm volatile("mma.sync.aligned.m16n8k16.row.col.f32.bf16.bf16.f32 "
                 "{%0,%1,%2,%3}, {%4,%5,%6,%7}, {%8,%9}, {%0,%1,%2,%3};"
                 : "+f"(d[0]), "+f"(d[1]), "+f"(d[2]), "+f"(d[3])
                 : "r"(a[0]), "r"(a[1]), "r"(a[2]), "r"(a[3]), "r"(b[0]), "r"(b[1]));
}
__device__ __forceinline__ unsigned pk2(float a, float b) {
    __nv_bfloat162 t = __floats2bfloat162_rn(a, b);
    return *reinterpret_cast<unsigned*>(&t);
}
__device__ __forceinline__ float resid(float a) {
    return a - __bfloat162float(__float2bfloat16(a));
}

// ---------------- conversion kernels ---------------------------------------
// seg 0/1/2 -> g_xh/g_xl segment; seg 3 -> g_woh/g_wol
__global__ void split_f32(const float* __restrict__ in, int seg, int n4) {
    int i = blockIdx.x * blockDim.x + threadIdx.x;
    if (i >= n4) return;
    __nv_bfloat16 *hi, *lo;
    if (seg < 3) { hi = g_xh + (size_t)seg*BS_*D_; lo = g_xl + (size_t)seg*BS_*D_; }
    else         { hi = g_woh; lo = g_wol; }
    float4 v = reinterpret_cast<const float4*>(in)[i];
    uint2 uh, ul;
    uh.x = pk2(v.x, v.y);               uh.y = pk2(v.z, v.w);
    ul.x = pk2(resid(v.x), resid(v.y)); ul.y = pk2(resid(v.z), resid(v.w));
    reinterpret_cast<uint2*>(hi)[i] = uh;
    reinterpret_cast<uint2*>(lo)[i] = ul;
}

// Wq/Wk/Wv [H][D][DK] -> [mat][H*DK][D] (hi/lo), tiled transpose
__global__ void conv_w(const float* __restrict__ Wq, const float* __restrict__ Wk,
                       const float* __restrict__ Wv) {
    __shared__ float t[32][33];
    const int mat = blockIdx.z >> 4;
    const int h   = blockIdx.z & 15;
    const float* W = (mat == 0) ? Wq : (mat == 1) ? Wk : Wv;
    const int d0 = blockIdx.x * 32, k0 = blockIdx.y * 32;
    const int tx = threadIdx.x, ty = threadIdx.y;
    #pragma unroll
    for (int i = 0; i < 4; i++)
        t[ty + 8*i][tx] = W[h * (D_*DK_) + (d0 + ty + 8*i) * DK_ + k0 + tx];
    __syncthreads();
    #pragma unroll
    for (int i = 0; i < 4; i++) {
        float v = t[tx][ty + 8*i];
        int o = mat * (HD_*D_) + (h * DK_ + k0 + ty + 8*i) * D_ + d0 + tx;
        g_wh[o] = __float2bfloat16(v);
        g_wl[o] = __float2bfloat16(resid(v));
    }
}

// g_att [B,H,S,DK] -> [m][j] (hi/lo)
__global__ void conv_att() {
    int i = blockIdx.x * blockDim.x + threadIdx.x;   // float4 index
    if (i >= BS_*HD_/4) return;
    int r  = i >> 4;
    int c4 = i & 15;
    int bh = r >> 11, s = r & (S_-1);
    int b  = bh >> 4, h = bh & 15;
    int m  = b * S_ + s;
    int j  = h * DK_ + c4 * 4;
    float4 v = reinterpret_cast<const float4*>(g_att)[i];
    uint2 uh, ul;
    uh.x = pk2(v.x, v.y);               uh.y = pk2(v.z, v.w);
    ul.x = pk2(resid(v.x), resid(v.y)); ul.y = pk2(resid(v.z), resid(v.w));
    int o = (m * HD_ + j) >> 2;
    reinterpret_cast<uint2*>(g_ah)[o] = uh;
    reinterpret_cast<uint2*>(g_al)[o] = ul;
}

// ---------------- warp-MMA split-bf16 GEMM ---------------------------------
// C[m][n] = sum_k A[m][k]*B[n][k]; A/B bf16 hi+lo, K-major, K=1024.
// CTA 128x128, BK=32, 8 warps (64x32 each), cp.async double buffer.
#define BK   32
#define NCH  (D_/BK)         // 32
#define ROWB 80              // smem bytes per 32-elt row (padded, ldmatrix conflict-free)
#define TILEB (128*ROWB)     // 10240
#define STAGEB (4*TILEB)     // 40960: Ah|Al|Bh|Bl
#define SMEM_GEMM (2*STAGEB) // 81920

__global__ void __launch_bounds__(256) gemm_mma(const float* __restrict__ bias,
                                                float* __restrict__ outp, int mode)
{
    extern __shared__ __align__(128) char smem[];
    const int tid = threadIdx.x;
    const int z = blockIdx.z;

    const __nv_bfloat16 *Ah, *Al, *Bh, *Bl;
    float* O;
    if (mode == 0) {
        Ah = g_xh + (size_t)z*BS_*D_;  Al = g_xl + (size_t)z*BS_*D_;
        Bh = g_wh + (size_t)z*HD_*D_;  Bl = g_wl + (size_t)z*HD_*D_;
        O  = (z == 0) ? g_q : (z == 1) ? g_k : g_v;
    } else {
        Ah = g_ah; Al = g_al; Bh = g_woh; Bl = g_wol; O = outp;
    }
    const int n0 = blockIdx.x * 128;
    const int m0 = blockIdx.y * 128;
    const uint32_t sb = smem_u32(smem);

    const int lane = tid & 31, wid = tid >> 5;
    const int wr = wid >> 2, wc = wid & 3;       // warp 64-row block, 32-col block
    const int lr = lane & 7, lq = lane >> 3;

    float acc[4][4][4];
    #pragma unroll
    for (int mi = 0; mi < 4; mi++)
        #pragma unroll
        for (int ni = 0; ni < 4; ni++)
            #pragma unroll
            for (int r = 0; r < 4; r++) acc[mi][ni][r] = 0.f;

    // ---- cp.async chunk issue: 512 16B-lines per operand tile -------------
    #define ISSUE(c) do {                                                     \
        const uint32_t st = sb + ((c) & 1) * STAGEB;                          \
        const int k0 = (c) * BK;                                              \
        _Pragma("unroll")                                                     \
        for (int it = 0; it < 2; it++) {                                      \
            const int e = tid + it * 256;                                     \
            const int row = e >> 2, c16 = e & 3;                              \
            const uint32_t so = row * ROWB + c16 * 16;                        \
            cp16(st + so,           Ah + (size_t)(m0+row)*D_ + k0 + c16*8);   \
            cp16(st + TILEB + so,   Al + (size_t)(m0+row)*D_ + k0 + c16*8);   \
            cp16(st + 2*TILEB + so, Bh + (size_t)(n0+row)*D_ + k0 + c16*8);   \
            cp16(st + 3*TILEB + so, Bl + (size_t)(n0+row)*D_ + k0 + c16*8);   \
        }                                                                     \
        asm volatile("cp.async.commit_group;" ::: "memory");                  \
    } while (0)

    ISSUE(0);
    ISSUE(1);

    #pragma unroll 1
    for (int c = 0; c < NCH; c++) {
        if (c < NCH - 1) asm volatile("cp.async.wait_group 1;" ::: "memory");
        else             asm volatile("cp.async.wait_group 0;" ::: "memory");
        __syncthreads();
        const uint32_t st = sb + (c & 1) * STAGEB;

        #pragma unroll
        for (int ks = 0; ks < 2; ks++) {
            uint32_t ah[4][4], al[4][4];
            #pragma unroll
            for (int mi = 0; mi < 4; mi++) {
                const int arow = wr*64 + mi*16 + (lq & 1)*8 + lr;
                const uint32_t aoff = (uint32_t)(arow*ROWB + (ks*16 + (lq >> 1)*8)*2);
                ldsm4(ah[mi], st + aoff);
                ldsm4(al[mi], st + TILEB + aoff);
            }
            #pragma unroll
            for (int ni = 0; ni < 4; ni++) {
                const int brow = wc*32 + ni*8 + lr;
                const uint32_t boff = (uint32_t)(brow*ROWB + (ks*16 + (lq & 1)*8)*2);
                uint32_t bh[2], bl[2];
                ldsm2(bh, st + 2*TILEB + boff);
                ldsm2(bl, st + 3*TILEB + boff);
                #pragma unroll
                for (int mi = 0; mi < 4; mi++) {
                    mma16816(acc[mi][ni], ah[mi], bh);   // hi*hi
                    mma16816(acc[mi][ni], ah[mi], bl);   // hi*lo
                    mma16816(acc[mi][ni], al[mi], bh);   // lo*hi
                }
            }
        }
        __syncthreads();
        if (c + 2 < NCH) ISSUE(c + 2);
    }

    // ---- epilogue ----------------------------------------------------------
    #pragma unroll
    for (int mi = 0; mi < 4; mi++) {
        const int row = m0 + wr*64 + mi*16 + (lane >> 2);
        #pragma unroll
        for (int ni = 0; ni < 4; ni++) {
            const int col = n0 + wc*32 + ni*8 + (lane & 3)*2;
            float2 v0 = make_float2(acc[mi][ni][0], acc[mi][ni][1]);
            float2 v1 = make_float2(acc[mi][ni][2], acc[mi][ni][3]);
            if (mode == 0) {
                const int b = row >> 11, s = row & (S_-1);
                const int h = col >> 6, kc = col & 63;
                float* p = &O[(((size_t)(b*H_ + h))*S_ + s)*DK_ + kc];
                *reinterpret_cast<float2*>(p) = v0;
                *reinterpret_cast<float2*>(p + 8*DK_) = v1;   // row+8, same b/h
            } else {
                float2 bv = *reinterpret_cast<const float2*>(&bias[col]);
                v0.x += bv.x; v0.y += bv.y; v1.x += bv.x; v1.y += bv.y;
                *reinterpret_cast<float2*>(&O[(size_t)row*D_ + col]) = v0;
                *reinterpret_cast<float2*>(&O[(size_t)(row+8)*D_ + col]) = v1;
            }
        }
    }
}

// ---------------- causal flash attention (fp32 SIMT, known-good) -----------
__global__ void __launch_bounds__(256) attn_kernel()
{
    __shared__ __align__(16) float Qs[64][64];
    __shared__ __align__(16) float KPs[64][64];
    __shared__ __align__(16) float Vs[64][64];

    const int qt = blockIdx.x;
    const int bh = blockIdx.y;
    const int t  = threadIdx.x;
    const int tx = t & 15, ty = t >> 4;

    const float* qbase = g_q + (size_t)bh * S_ * DK_;
    const float* kbase = g_k + (size_t)bh * S_ * DK_;
    const float* vbase = g_v + (size_t)bh * S_ * DK_;
    const int q0 = qt * 64;

    #pragma unroll
    for (int it = 0; it < 4; it++) {
        const int e = t + it * 256;
        const int row = e >> 4, dc = (e & 15) * 4;
        float4 v = *reinterpret_cast<const float4*>(&qbase[(q0 + row) * DK_ + dc]);
        Qs[dc+0][row] = v.x; Qs[dc+1][row] = v.y; Qs[dc+2][row] = v.z; Qs[dc+3][row] = v.w;
    }

    float m_i[4], l_i[4], o[4][4];
    #pragma unroll
    for (int i = 0; i < 4; i++) {
        m_i[i] = -1e30f; l_i[i] = 0.f;
        #pragma unroll
        for (int j = 0; j < 4; j++) o[i][j] = 0.f;
    }
    const float scale = 0.125f;

    for (int kt = 0; kt <= qt; kt++) {
        __syncthreads();
        const int k0 = kt * 64;
        #pragma unroll
        for (int it = 0; it < 4; it++) {
            const int e = t + it * 256;
            const int row = e >> 4, dc = (e & 15) * 4;
            float4 kv = *reinterpret_cast<const float4*>(&kbase[(k0 + row) * DK_ + dc]);
            KPs[dc+0][row] = kv.x; KPs[dc+1][row] = kv.y;
            KPs[dc+2][row] = kv.z; KPs[dc+3][row] = kv.w;
            float4 vv = *reinterpret_cast<const float4*>(&vbase[(k0 + row) * DK_ + dc]);
            *reinterpret_cast<float4*>(&Vs[row][dc]) = vv;
        }
        __syncthreads();

        float s[4][4];
        #pragma unroll
        for (int i = 0; i < 4; i++)
            #pragma unroll
            for (int j = 0; j < 4; j++) s[i][j] = 0.f;

        #pragma unroll 8
        for (int d = 0; d < 64; d++) {
            float qv[4], kv[4];
            #pragma unroll
            for (int i = 0; i < 4; i++) qv[i] = Qs[d][ty * 4 + i];
            #pragma unroll
            for (int j = 0; j < 4; j++) kv[j] = KPs[d][tx * 4 + j];
            #pragma unroll
            for (int i = 0; i < 4; i++)
                #pragma unroll
                for (int j = 0; j < 4; j++)
                    s[i][j] += qv[i] * kv[j];
        }

        const bool diag = (kt == qt);
        #pragma unroll
        for (int i = 0; i < 4; i++)
            #pragma unroll
            for (int j = 0; j < 4; j++) {
                s[i][j] *= scale;
                if (diag && (tx * 4 + j) > (ty * 4 + i)) s[i][j] = -1e30f;
            }

        #pragma unroll
        for (int i = 0; i < 4; i++) {
            float tm = s[i][0];
            #pragma unroll
            for (int j = 1; j < 4; j++) tm = fmaxf(tm, s[i][j]);
            #pragma unroll
            for (int off = 8; off > 0; off >>= 1)
                tm = fmaxf(tm, __shfl_xor_sync(0xffffffffu, tm, off));
            const float mnew = fmaxf(m_i[i], tm);
            const float corr = __expf(m_i[i] - mnew);
            float rs = 0.f;
            #pragma unroll
            for (int j = 0; j < 4; j++) {
                const float p = __expf(s[i][j] - mnew);
                s[i][j] = p; rs += p;
            }
            #pragma unroll
            for (int off = 8; off > 0; off >>= 1)
                rs += __shfl_xor_sync(0xffffffffu, rs, off);
            l_i[i] = l_i[i] * corr + rs;
            m_i[i] = mnew;
            #pragma unroll
            for (int j = 0; j < 4; j++) o[i][j] *= corr;
        }

        __syncthreads();
        #pragma unroll
        for (int i = 0; i < 4; i++)
            #pragma unroll
            for (int j = 0; j < 4; j++)
                KPs[ty * 4 + i][tx * 4 + j] = s[i][j];
        __syncthreads();

        #pragma unroll 8
        for (int jj = 0; jj < 64; jj++) {
            float pv[4], vv[4];
            #pragma unroll
            for (int i = 0; i < 4; i++) pv[i] = KPs[ty * 4 + i][jj];
            #pragma unroll
            for (int j = 0; j < 4; j++) vv[j] = Vs[jj][tx * 4 + j];
            #pragma unroll
            for (int i = 0; i < 4; i++)
                #pragma unroll
                for (int j = 0; j < 4; j++)
                    o[i][j] += pv[i] * vv[j];
        }
    }

    float* abase = g_att + (size_t)bh * S_ * DK_;
    #pragma unroll
    for (int i = 0; i < 4; i++) {
        const float inv = 1.0f / l_i[i];
        const int row = q0 + ty * 4 + i;
        float4 v = make_float4(o[i][0]*inv, o[i][1]*inv, o[i][2]*inv, o[i][3]*inv);
        *reinterpret_cast<float4*>(&abase[row * DK_ + tx * 4]) = v;
    }
}

// ---------------- launch ----------------------------------------------------
extern "C" void kernel_launch(void* const* d_in, const int* in_sizes, int n_in,
                              void* d_out, int out_size)
{
    const float* query = (const float*)d_in[0];
    const float* key   = (const float*)d_in[1];
    const float* value = (const float*)d_in[2];
    const float* Wq    = (const float*)d_in[3];
    const float* Wk    = (const float*)d_in[4];
    const float* Wv    = (const float*)d_in[5];
    const float* Wo    = (const float*)d_in[6];
    const float* bo    = (const float*)d_in[7];
    float* out = (float*)d_out;

    static bool attr_done = false;
    if (!attr_done) {
        cudaFuncSetAttribute(gemm_mma, cudaFuncAttributeMaxDynamicSharedMemorySize, SMEM_GEMM);
        attr_done = true;
    }

    const int n4x = BS_ * D_ / 4;      // 1,048,576
    const int n4w = D_ * HD_ / 4;      // 262,144
    split_f32<<<n4x/256, 256>>>(query, 0, n4x);
    split_f32<<<n4x/256, 256>>>(key,   1, n4x);
    split_f32<<<n4x/256, 256>>>(value, 2, n4x);
    split_f32<<<n4w/256, 256>>>(Wo,    3, n4w);
    conv_w<<<dim3(D_/32, DK_/32, 3*H_), dim3(32, 8)>>>(Wq, Wk, Wv);

    gemm_mma<<<dim3(HD_/128, BS_/128, 3), 256, SMEM_GEMM>>>(nullptr, nullptr, 0);

    attn_kernel<<<dim3(S_/64, B_*H_), 256>>>();

    conv_att<<<(BS_*HD_/4)/256, 256>>>();

    gemm_mma<<<dim3(D_/128, BS_/128, 1), 256, SMEM_GEMM>>>(bo, out, 1);
}

// round 13
// speedup vs baseline: 2.9102x; 1.9050x over previous
#include <cuda_runtime.h>
#include <cuda_bf16.h>
#include <cstdint>

#define B_  2
#define S_  2048
#define D_  1024
#define H_  16
#define DK_ 64
#define BS_ (B_*S_)    // 4096
#define HD_ (H_*DK_)   // 1024

// ---------------- scratch (__device__ globals; no allocs allowed) ----------
__device__ __nv_bfloat16 g_xh[3*BS_*D_];   // q,k,v inputs, hi
__device__ __nv_bfloat16 g_xl[3*BS_*D_];   // lo
__device__ __nv_bfloat16 g_wh[3*HD_*D_];   // Wq/Wk/Wv transposed to [n][d], hi
__device__ __nv_bfloat16 g_wl[3*HD_*D_];
__device__ __nv_bfloat16 g_qh[B_*H_*S_*DK_];  // Q proj (pre-scaled 0.125) [bh][s][d]
__device__ __nv_bfloat16 g_ql[B_*H_*S_*DK_];
__device__ __nv_bfloat16 g_kh[B_*H_*S_*DK_];  // K proj [bh][s][d]
__device__ __nv_bfloat16 g_kl[B_*H_*S_*DK_];
__device__ __nv_bfloat16 g_vth[B_*H_*S_*DK_]; // V proj TRANSPOSED [bh][d][s]
__device__ __nv_bfloat16 g_vtl[B_*H_*S_*DK_];
__device__ __nv_bfloat16 g_ah[BS_*HD_];    // attention output [m][j]
__device__ __nv_bfloat16 g_al[BS_*HD_];
__device__ __nv_bfloat16 g_woh[D_*HD_];    // Wo [n][j] (K-major)
__device__ __nv_bfloat16 g_wol[D_*HD_];

// ---------------- helpers ---------------------------------------------------
__device__ __forceinline__ uint32_t smem_u32(const void* p) {
    uint32_t a;
    asm("{ .reg .u64 t; cvta.to.shared.u64 t, %1; cvt.u32.u64 %0, t; }" : "=r"(a) : "l"(p));
    return a;
}
__device__ __forceinline__ void cp16(uint32_t s, const void* g) {
    asm volatile("cp.async.cg.shared.global [%0], [%1], 16;" :: "r"(s), "l"(g) : "memory");
}
__device__ __forceinline__ void ldsm4(uint32_t* r, uint32_t a) {
    asm volatile("ldmatrix.sync.aligned.m8n8.x4.shared.b16 {%0,%1,%2,%3}, [%4];"
                 : "=r"(r[0]), "=r"(r[1]), "=r"(r[2]), "=r"(r[3]) : "r"(a));
}
__device__ __forceinline__ void ldsm2(uint32_t* r, uint32_t a) {
    asm volatile("ldmatrix.sync.aligned.m8n8.x2.shared.b16 {%0,%1}, [%2];"
                 : "=r"(r[0]), "=r"(r[1]) : "r"(a));
}
__device__ __forceinline__ void mma16816(float* d, const uint32_t* a, const uint32_t* b) {
    asm volatile("mma.sync.aligned.m16n8k16.row.col.f32.bf16.bf16.f32 "
                 "{%0,%1,%2,%3}, {%4,%5,%6,%7}, {%8,%9}, {%0,%1,%2,%3};"
                 : "+f"(d[0]), "+f"(d[1]), "+f"(d[2]), "+f"(d[3])
                 : "r"(a[0]), "r"(a[1]), "r"(a[2]), "r"(a[3]), "r"(b[0]), "r"(b[1]));
}
__device__ __forceinline__ unsigned pk2(float a, float b) {
    __nv_bfloat162 t = __floats2bfloat162_rn(a, b);
    return *reinterpret_cast<unsigned*>(&t);
}
__device__ __forceinline__ float resid(float a) {
    return a - __bfloat162float(__float2bfloat16(a));
}

// ---------------- conversion kernels ---------------------------------------
__global__ void split_f32(const float* __restrict__ in, int seg, int n4) {
    int i = blockIdx.x * blockDim.x + threadIdx.x;
    if (i >= n4) return;
    __nv_bfloat16 *hi, *lo;
    if (seg < 3) { hi = g_xh + (size_t)seg*BS_*D_; lo = g_xl + (size_t)seg*BS_*D_; }
    else         { hi = g_woh; lo = g_wol; }
    float4 v = reinterpret_cast<const float4*>(in)[i];
    uint2 uh, ul;
    uh.x = pk2(v.x, v.y);               uh.y = pk2(v.z, v.w);
    ul.x = pk2(resid(v.x), resid(v.y)); ul.y = pk2(resid(v.z), resid(v.w));
    reinterpret_cast<uint2*>(hi)[i] = uh;
    reinterpret_cast<uint2*>(lo)[i] = ul;
}

// Wq/Wk/Wv [H][D][DK] -> [mat][H*DK][D] (hi/lo), tiled transpose
__global__ void conv_w(const float* __restrict__ Wq, const float* __restrict__ Wk,
                       const float* __restrict__ Wv) {
    __shared__ float t[32][33];
    const int mat = blockIdx.z >> 4;
    const int h   = blockIdx.z & 15;
    const float* W = (mat == 0) ? Wq : (mat == 1) ? Wk : Wv;
    const int d0 = blockIdx.x * 32, k0 = blockIdx.y * 32;
    const int tx = threadIdx.x, ty = threadIdx.y;
    #pragma unroll
    for (int i = 0; i < 4; i++)
        t[ty + 8*i][tx] = W[h * (D_*DK_) + (d0 + ty + 8*i) * DK_ + k0 + tx];
    __syncthreads();
    #pragma unroll
    for (int i = 0; i < 4; i++) {
        float v = t[tx][ty + 8*i];
        int o = mat * (HD_*D_) + (h * DK_ + k0 + ty + 8*i) * D_ + d0 + tx;
        g_wh[o] = __float2bfloat16(v);
        g_wl[o] = __float2bfloat16(resid(v));
    }
}

// ---------------- warp-MMA split-bf16 GEMM ---------------------------------
// C[m][n] = sum_k A[m][k]*B[n][k]; A/B bf16 hi+lo, K-major, K=1024.
// CTA 128x128, BK=32, 8 warps (64x32 each), cp.async double buffer.
// mode 0: epilogue emits bf16 hi/lo to g_q*/g_k*/g_vt* (Q scaled by 0.125,
//         V transposed). mode 1: fp32 + bias to outp.
#define BK   32
#define NCH  (D_/BK)         // 32
#define ROWB 80
#define TILEB (128*ROWB)     // 10240
#define STAGEB (4*TILEB)     // 40960
#define SMEM_GEMM (2*STAGEB) // 81920

__global__ void __launch_bounds__(256) gemm_mma(const float* __restrict__ bias,
                                                float* __restrict__ outp, int mode)
{
    extern __shared__ __align__(128) char smem[];
    const int tid = threadIdx.x;
    const int z = blockIdx.z;

    const __nv_bfloat16 *Ah, *Al, *Bh, *Bl;
    if (mode == 0) {
        Ah = g_xh + (size_t)z*BS_*D_;  Al = g_xl + (size_t)z*BS_*D_;
        Bh = g_wh + (size_t)z*HD_*D_;  Bl = g_wl + (size_t)z*HD_*D_;
    } else {
        Ah = g_ah; Al = g_al; Bh = g_woh; Bl = g_wol;
    }
    const int n0 = blockIdx.x * 128;
    const int m0 = blockIdx.y * 128;
    const uint32_t sb = smem_u32(smem);

    const int lane = tid & 31, wid = tid >> 5;
    const int wr = wid >> 2, wc = wid & 3;
    const int lr = lane & 7, lq = lane >> 3;

    float acc[4][4][4];
    #pragma unroll
    for (int mi = 0; mi < 4; mi++)
        #pragma unroll
        for (int ni = 0; ni < 4; ni++)
            #pragma unroll
            for (int r = 0; r < 4; r++) acc[mi][ni][r] = 0.f;

    #define ISSUE(c) do {                                                     \
        const uint32_t st = sb + ((c) & 1) * STAGEB;                          \
        const int k0 = (c) * BK;                                              \
        _Pragma("unroll")                                                     \
        for (int it = 0; it < 2; it++) {                                      \
            const int e = tid + it * 256;                                     \
            const int row = e >> 2, c16 = e & 3;                              \
            const uint32_t so = row * ROWB + c16 * 16;                        \
            cp16(st + so,           Ah + (size_t)(m0+row)*D_ + k0 + c16*8);   \
            cp16(st + TILEB + so,   Al + (size_t)(m0+row)*D_ + k0 + c16*8);   \
            cp16(st + 2*TILEB + so, Bh + (size_t)(n0+row)*D_ + k0 + c16*8);   \
            cp16(st + 3*TILEB + so, Bl + (size_t)(n0+row)*D_ + k0 + c16*8);   \
        }                                                                     \
        asm volatile("cp.async.commit_group;" ::: "memory");                  \
    } while (0)

    ISSUE(0);
    ISSUE(1);

    #pragma unroll 1
    for (int c = 0; c < NCH; c++) {
        if (c < NCH - 1) asm volatile("cp.async.wait_group 1;" ::: "memory");
        else             asm volatile("cp.async.wait_group 0;" ::: "memory");
        __syncthreads();
        const uint32_t st = sb + (c & 1) * STAGEB;

        #pragma unroll
        for (int ks = 0; ks < 2; ks++) {
            uint32_t ah[4][4], al[4][4];
            #pragma unroll
            for (int mi = 0; mi < 4; mi++) {
                const int arow = wr*64 + mi*16 + (lq & 1)*8 + lr;
                const uint32_t aoff = (uint32_t)(arow*ROWB + (ks*16 + (lq >> 1)*8)*2);
                ldsm4(ah[mi], st + aoff);
                ldsm4(al[mi], st + TILEB + aoff);
            }
            #pragma unroll
            for (int ni = 0; ni < 4; ni++) {
                const int brow = wc*32 + ni*8 + lr;
                const uint32_t boff = (uint32_t)(brow*ROWB + (ks*16 + (lq & 1)*8)*2);
                uint32_t bh[2], bl[2];
                ldsm2(bh, st + 2*TILEB + boff);
                ldsm2(bl, st + 3*TILEB + boff);
                #pragma unroll
                for (int mi = 0; mi < 4; mi++) {
                    mma16816(acc[mi][ni], ah[mi], bh);
                    mma16816(acc[mi][ni], ah[mi], bl);
                    mma16816(acc[mi][ni], al[mi], bh);
                }
            }
        }
        __syncthreads();
        if (c + 2 < NCH) ISSUE(c + 2);
    }

    // ---- epilogue ----------------------------------------------------------
    const float sc = (mode == 0 && z == 0) ? 0.125f : 1.f;
    #pragma unroll
    for (int mi = 0; mi < 4; mi++) {
        const int row = m0 + wr*64 + mi*16 + (lane >> 2);
        #pragma unroll
        for (int ni = 0; ni < 4; ni++) {
            const int col = n0 + wc*32 + ni*8 + (lane & 3)*2;
            float c0 = acc[mi][ni][0]*sc, c1 = acc[mi][ni][1]*sc;
            float c2 = acc[mi][ni][2]*sc, c3 = acc[mi][ni][3]*sc;
            if (mode == 0) {
                const int b = row >> 11, s = row & (S_-1);
                const int h = col >> 6, d = col & 63;
                if (z < 2) {
                    __nv_bfloat16* Ph = (z == 0) ? g_qh : g_kh;
                    __nv_bfloat16* Pl = (z == 0) ? g_ql : g_kl;
                    const size_t off = ((size_t)(b*H_ + h)*S_ + s)*DK_ + d;
                    *reinterpret_cast<unsigned*>(Ph + off) = pk2(c0, c1);
                    *reinterpret_cast<unsigned*>(Pl + off) = pk2(resid(c0), resid(c1));
                    *reinterpret_cast<unsigned*>(Ph + off + 8*DK_) = pk2(c2, c3);
                    *reinterpret_cast<unsigned*>(Pl + off + 8*DK_) = pk2(resid(c2), resid(c3));
                } else {
                    // V transposed: [bh][d][s]
                    const size_t base = ((size_t)(b*H_ + h)*DK_ + d)*S_ + s;
                    g_vth[base]        = __float2bfloat16(c0);
                    g_vtl[base]        = __float2bfloat16(resid(c0));
                    g_vth[base + S_]   = __float2bfloat16(c1);
                    g_vtl[base + S_]   = __float2bfloat16(resid(c1));
                    g_vth[base + 8]    = __float2bfloat16(c2);
                    g_vtl[base + 8]    = __float2bfloat16(resid(c2));
                    g_vth[base + S_+8] = __float2bfloat16(c3);
                    g_vtl[base + S_+8] = __float2bfloat16(resid(c3));
                }
            } else {
                float2 bv = *reinterpret_cast<const float2*>(&bias[col]);
                float2 v0 = make_float2(c0 + bv.x, c1 + bv.y);
                float2 v1 = make_float2(c2 + bv.x, c3 + bv.y);
                *reinterpret_cast<float2*>(&outp[(size_t)row*D_ + col]) = v0;
                *reinterpret_cast<float2*>(&outp[(size_t)(row+8)*D_ + col]) = v1;
            }
        }
    }
}

// ---------------- tensor-core causal flash attention -----------------------
// CTA: 128 q rows x (b,h); 8 warps x 16 rows. Key blocks of 64.
// S = QK^T (3-MMA hi/lo split, fp32 frags, Q pre-scaled), causal mask,
// online softmax, P repacked in-register to bf16 hi/lo -> PV (3-MMA split).
#define VROW 144                 // 64 bf16 = 128B + 16B pad (ldmatrix conflict-free)
#define KTILE (64*VROW)          // 9216
#define ASTAGE (4*KTILE)         // Kh|Kl|Vth|Vtl = 36864
#define SMEM_ATT (2*ASTAGE)      // 73728

__global__ void __launch_bounds__(256) attn_mma()
{
    extern __shared__ __align__(128) char smem[];
    const uint32_t sb = smem_u32(smem);
    const int tid = threadIdx.x, lane = tid & 31, wid = tid >> 5;
    const int lr = lane & 7, lq = lane >> 3;
    const int qt = blockIdx.x, bh = blockIdx.y;
    const int q0 = qt * 128;
    const size_t hb = (size_t)bh * S_ * DK_;
    const __nv_bfloat16* Qh = g_qh + hb;
    const __nv_bfloat16* Ql = g_ql + hb;
    const __nv_bfloat16* Kh = g_kh + hb;
    const __nv_bfloat16* Kl = g_kl + hb;
    const __nv_bfloat16* Vh = g_vth + hb;   // [64][S]
    const __nv_bfloat16* Vl = g_vtl + hb;

    // ---- stage Q tile (hi/lo) through smem, build A fragments -------------
    #pragma unroll
    for (int it = 0; it < 4; it++) {
        const int e = tid + it * 256;       // 0..1023 = 128 rows x 8 lines
        const int row = e >> 3, c16 = e & 7;
        uint4 vh = *reinterpret_cast<const uint4*>(Qh + (size_t)(q0+row)*DK_ + c16*8);
        uint4 vl = *reinterpret_cast<const uint4*>(Ql + (size_t)(q0+row)*DK_ + c16*8);
        *reinterpret_cast<uint4*>(smem + row*VROW + c16*16) = vh;
        *reinterpret_cast<uint4*>(smem + 128*VROW + row*VROW + c16*16) = vl;
    }
    __syncthreads();
    uint32_t qa[4][4], qal[4][4];
    {
        const int arow = wid*16 + (lq & 1)*8 + lr;
        #pragma unroll
        for (int ks = 0; ks < 4; ks++) {
            const uint32_t aoff = (uint32_t)(arow*VROW + (ks*16 + (lq >> 1)*8)*2);
            ldsm4(qa[ks],  sb + aoff);
            ldsm4(qal[ks], sb + 128*VROW + aoff);
        }
    }
    __syncthreads();

    float o[8][4];
    #pragma unroll
    for (int ni = 0; ni < 8; ni++)
        #pragma unroll
        for (int r = 0; r < 4; r++) o[ni][r] = 0.f;
    float m0 = -1e30f, m1 = -1e30f, l0 = 0.f, l1 = 0.f;

    const int nb = 2*qt + 2;
    const int qtop = q0 + wid*16;          // warp's first q row
    const int r0 = qtop + (lane >> 2);
    const int r1 = r0 + 8;

    #define AISSUE(bb_) do {                                                  \
        const uint32_t st_ = sb + ((bb_) & 1) * ASTAGE;                       \
        const int k0_ = (bb_) * 64;                                           \
        _Pragma("unroll")                                                     \
        for (int it = 0; it < 2; it++) {                                      \
            const int e = tid + it * 256;      /* 0..511 = 64 rows x 8 */     \
            const int row = e >> 3, c16 = e & 7;                              \
            const uint32_t so = row*VROW + c16*16;                            \
            cp16(st_ + so,           Kh + (size_t)(k0_+row)*DK_ + c16*8);     \
            cp16(st_ + KTILE + so,   Kl + (size_t)(k0_+row)*DK_ + c16*8);     \
            cp16(st_ + 2*KTILE + so, Vh + (size_t)row*S_ + k0_ + c16*8);      \
            cp16(st_ + 3*KTILE + so, Vl + (size_t)row*S_ + k0_ + c16*8);      \
        }                                                                     \
        asm volatile("cp.async.commit_group;" ::: "memory");                  \
    } while (0)

    AISSUE(0);
    AISSUE(1);

    #pragma unroll 1
    for (int b = 0; b < nb; b++) {
        if (b < nb - 1) asm volatile("cp.async.wait_group 1;" ::: "memory");
        else            asm volatile("cp.async.wait_group 0;" ::: "memory");
        __syncthreads();

        if (b*64 <= qtop + 15) {           // block not fully above-diagonal
            const uint32_t st = sb + (b & 1) * ASTAGE;

            // ---- S = Q K^T -------------------------------------------------
            float sacc[8][4];
            #pragma unroll
            for (int ni = 0; ni < 8; ni++)
                #pragma unroll
                for (int r = 0; r < 4; r++) sacc[ni][r] = 0.f;

            #pragma unroll
            for (int ni = 0; ni < 8; ni++) {
                const uint32_t brow = ni*8 + lr;
                #pragma unroll
                for (int ks = 0; ks < 4; ks++) {
                    const uint32_t boff = brow*VROW + (ks*16 + (lq & 1)*8)*2;
                    uint32_t kb[2], kbl[2];
                    ldsm2(kb,  st + boff);
                    ldsm2(kbl, st + KTILE + boff);
                    mma16816(sacc[ni], qa[ks],  kb);
                    mma16816(sacc[ni], qa[ks],  kbl);
                    mma16816(sacc[ni], qal[ks], kb);
                }
            }

            // ---- causal mask (diagonal block only) -------------------------
            if (b*64 + 63 > qtop) {
                #pragma unroll
                for (int ni = 0; ni < 8; ni++) {
                    const int c = b*64 + ni*8 + (lane & 3)*2;
                    if (c     > r0) sacc[ni][0] = -1e30f;
                    if (c + 1 > r0) sacc[ni][1] = -1e30f;
                    if (c     > r1) sacc[ni][2] = -1e30f;
                    if (c + 1 > r1) sacc[ni][3] = -1e30f;
                }
            }

            // ---- online softmax -------------------------------------------
            float tm0 = -1e30f, tm1 = -1e30f;
            #pragma unroll
            for (int ni = 0; ni < 8; ni++) {
                tm0 = fmaxf(tm0, fmaxf(sacc[ni][0], sacc[ni][1]));
                tm1 = fmaxf(tm1, fmaxf(sacc[ni][2], sacc[ni][3]));
            }
            #pragma unroll
            for (int off = 1; off < 4; off <<= 1) {
                tm0 = fmaxf(tm0, __shfl_xor_sync(0xffffffffu, tm0, off));
                tm1 = fmaxf(tm1, __shfl_xor_sync(0xffffffffu, tm1, off));
            }
            const float mn0 = fmaxf(m0, tm0), mn1 = fmaxf(m1, tm1);
            const float cr0 = __expf(m0 - mn0), cr1 = __expf(m1 - mn1);
            float rs0 = 0.f, rs1 = 0.f;
            #pragma unroll
            for (int ni = 0; ni < 8; ni++) {
                sacc[ni][0] = __expf(sacc[ni][0] - mn0);
                sacc[ni][1] = __expf(sacc[ni][1] - mn0);
                sacc[ni][2] = __expf(sacc[ni][2] - mn1);
                sacc[ni][3] = __expf(sacc[ni][3] - mn1);
                rs0 += sacc[ni][0] + sacc[ni][1];
                rs1 += sacc[ni][2] + sacc[ni][3];
            }
            #pragma unroll
            for (int off = 1; off < 4; off <<= 1) {
                rs0 += __shfl_xor_sync(0xffffffffu, rs0, off);
                rs1 += __shfl_xor_sync(0xffffffffu, rs1, off);
            }
            l0 = l0*cr0 + rs0;  l1 = l1*cr1 + rs1;
            m0 = mn0;           m1 = mn1;
            #pragma unroll
            for (int ni = 0; ni < 8; ni++) {
                o[ni][0] *= cr0; o[ni][1] *= cr0;
                o[ni][2] *= cr1; o[ni][3] *= cr1;
            }

            // ---- pack P (S-acc layout == A-frag layout) -------------------
            uint32_t pa[4][4], pal[4][4];
            #pragma unroll
            for (int kc = 0; kc < 4; kc++) {
                const float* t0 = sacc[2*kc];
                const float* t1 = sacc[2*kc + 1];
                pa[kc][0]  = pk2(t0[0], t0[1]);
                pa[kc][1]  = pk2(t0[2], t0[3]);
                pa[kc][2]  = pk2(t1[0], t1[1]);
                pa[kc][3]  = pk2(t1[2], t1[3]);
                pal[kc][0] = pk2(resid(t0[0]), resid(t0[1]));
                pal[kc][1] = pk2(resid(t0[2]), resid(t0[3]));
                pal[kc][2] = pk2(resid(t1[0]), resid(t1[1]));
                pal[kc][3] = pk2(resid(t1[2]), resid(t1[3]));
            }

            // ---- O += P V  (B = V^T tile [d][keys]) -----------------------
            #pragma unroll
            for (int ni = 0; ni < 8; ni++) {
                const uint32_t brow = ni*8 + lr;
                #pragma unroll
                for (int kc = 0; kc < 4; kc++) {
                    const uint32_t boff = brow*VROW + (kc*16 + (lq & 1)*8)*2;
                    uint32_t vb[2], vbl[2];
                    ldsm2(vb,  st + 2*KTILE + boff);
                    ldsm2(vbl, st + 3*KTILE + boff);
                    mma16816(o[ni], pa[kc],  vb);
                    mma16816(o[ni], pa[kc],  vbl);
                    mma16816(o[ni], pal[kc], vb);
                }
            }
        }

        __syncthreads();
        if (b + 2 < nb) AISSUE(b + 2);
    }

    // ---- epilogue: O/l -> bf16 hi/lo into [m][j] for oproj ----------------
    const float i0 = 1.f / l0, i1 = 1.f / l1;
    const int bb = bh >> 4, h = bh & 15;
    const size_t mg = (size_t)bb * S_ + r0;     // global m row for r0
    #pragma unroll
    for (int ni = 0; ni < 8; ni++) {
        const int j = h*64 + ni*8 + (lane & 3)*2;
        float a0 = o[ni][0]*i0, a1 = o[ni][1]*i0;
        float b0 = o[ni][2]*i1, b1 = o[ni][3]*i1;
        *reinterpret_cast<unsigned*>(g_ah + mg*HD_ + j)       = pk2(a0, a1);
        *reinterpret_cast<unsigned*>(g_al + mg*HD_ + j)       = pk2(resid(a0), resid(a1));
        *reinterpret_cast<unsigned*>(g_ah + (mg+8)*HD_ + j)   = pk2(b0, b1);
        *reinterpret_cast<unsigned*>(g_al + (mg+8)*HD_ + j)   = pk2(resid(b0), resid(b1));
    }
}

// ---------------- launch ----------------------------------------------------
extern "C" void kernel_launch(void* const* d_in, const int* in_sizes, int n_in,
                              void* d_out, int out_size)
{
    const float* query = (const float*)d_in[0];
    const float* key   = (const float*)d_in[1];
    const float* value = (const float*)d_in[2];
    const float* Wq    = (const float*)d_in[3];
    const float* Wk    = (const float*)d_in[4];
    const float* Wv    = (const float*)d_in[5];
    const float* Wo    = (const float*)d_in[6];
    const float* bo    = (const float*)d_in[7];
    float* out = (float*)d_out;

    static bool attr_done = false;
    if (!attr_done) {
        cudaFuncSetAttribute(gemm_mma, cudaFuncAttributeMaxDynamicSharedMemorySize, SMEM_GEMM);
        cudaFuncSetAttribute(attn_mma, cudaFuncAttributeMaxDynamicSharedMemorySize, SMEM_ATT);
        attr_done = true;
    }

    const int n4x = BS_ * D_ / 4;
    const int n4w = D_ * HD_ / 4;
    split_f32<<<n4x/256, 256>>>(query, 0, n4x);
    split_f32<<<n4x/256, 256>>>(key,   1, n4x);
    split_f32<<<n4x/256, 256>>>(value, 2, n4x);
    split_f32<<<n4w/256, 256>>>(Wo,    3, n4w);
    conv_w<<<dim3(D_/32, DK_/32, 3*H_), dim3(32, 8)>>>(Wq, Wk, Wv);

    gemm_mma<<<dim3(HD_/128, BS_/128, 3), 256, SMEM_GEMM>>>(nullptr, nullptr, 0);

    attn_mma<<<dim3(S_/128, B_*H_), 256, SMEM_ATT>>>();

    gemm_mma<<<dim3(D_/128, BS_/128, 1), 256, SMEM_GEMM>>>(bo, out, 1);
}